// round 12
// baseline (speedup 1.0000x reference)
#include <cuda_runtime.h>
#include <cstdint>

// CTC batch cost, forward (loss only). B=128, T=1024, C=256 (blank=255),
// Lmax=64, S=129.
//
//  - one warp (one CTA) per batch element; 5 states/thread (160 >= 129, masked)
//  - probability-domain recurrence, per-thread power-of-2 block-floating-point
//    scales (integer exponent bookkeeping), frontier-safe scan renorm t<128
//  - bulk-copy streaming ring: one 16KB cp.async.bulk per chunk, mbarrier
//    complete_tx per slot (R11, passed 45.4us @1.44e-6)
//  - THIS ROUND: SOFTWARE-PIPELINED HALO SHFL. n3/n4 are computed first
//    (local-only, ready +12cyc), shuffled immediately (they ARE the next
//    step's halos), then n0..n2 computed with current halos while the shfl
//    flies. Critical cycle drops 42 -> ~16 cyc/step. Pipeline restarts at
//    each renorm boundary (make_h).

#define T_DIM   1024
#define C_DIM   256
#define LMAX    64
#define PSTATES 5
#define CHUNK   16                        // rows per ring slot / wait
#define RINGC   8                         // ring slots
#define NCHUNK  (T_DIM / CHUNK)           // 64
#define SCANCH  8                         // chunks (t<128) using scan renorm
#define EPSF    1e-7f
#define MFLOOR  1e-37f
#define CHUNK_BYTES (CHUNK * C_DIM * 4)   // 16384
#define RING_BYTES  (RINGC * CHUNK_BYTES) // 131072

__global__ __launch_bounds__(32, 1)
void ctc_loss_kernel(const int*   __restrict__ y_true,   // [B, LMAX]
                     const float* __restrict__ y_pred,   // [B, T, C]
                     const int*   __restrict__ in_len,   // [B, 1]
                     const int*   __restrict__ lab_len,  // [B, 1]
                     float*       __restrict__ out)      // [B, 1]
{
    extern __shared__ __align__(128) float stage[];      // RINGC * 16KB ring
    __shared__ __align__(8) uint64_t mbar[RINGC];
    __shared__ float fin_a [32 * PSTATES];
    __shared__ float fin_lc[32];

    const int b   = blockIdx.x;
    const int tid = threadIdx.x;
    const char* __restrict__ gbase =
        (const char*)(y_pred + (size_t)b * T_DIM * C_DIM);
    const int L    = lab_len[b];
    const int Tlen = in_len[b];
    const int Smax = 2 * L + 1;
    const int* __restrict__ yb = y_true + b * LMAX;

    uint32_t stage_addr, mbar_addr;
    asm("{ .reg .u64 t; cvta.to.shared.u64 t, %1; cvt.u32.u64 %0, t; }"
        : "=r"(stage_addr) : "l"((const void*)stage));
    asm("{ .reg .u64 t; cvta.to.shared.u64 t, %1; cvt.u32.u64 %0, t; }"
        : "=r"(mbar_addr) : "l"((const void*)mbar));

    // ---- per-state constants ----
    int   cls[PSTATES];
    float vm [PSTATES];
    float evm[PSTATES];
    float m2 [PSTATES];
    #pragma unroll
    for (int j = 0; j < PSTATES; j++) {
        int s   = tid * PSTATES + j;
        int odd = s & 1;
        int li  = (s - 1) >> 1;
        int c   = (odd && li >= 0 && li < LMAX) ? yb[li] : (C_DIM - 1);
        bool valid = (s < Smax);
        cls[j] = c;
        vm [j] = valid ? 1.0f : 0.0f;
        evm[j] = valid ? EPSF : 0.0f;
        bool skip = odd && (s >= 3) && (li < LMAX) && (yb[li] != yb[li - 1]);
        m2 [j] = skip ? 1.0f : 0.0f;
    }

    // ---- mbarrier init ----
    if (tid == 0) {
        #pragma unroll
        for (int s = 0; s < RINGC; s++)
            asm volatile("mbarrier.init.shared.b64 [%0], 1;"
                         :: "r"(mbar_addr + s * 8) : "memory");
        asm volatile("fence.proxy.async.shared::cta;" ::: "memory");
    }
    __syncwarp();

    auto issue_chunk = [&](int c) {
        if (tid == 0 && c < NCHUNK) {
            uint32_t slot = (uint32_t)c & (RINGC - 1);
            uint32_t mb   = mbar_addr + slot * 8;
            uint32_t dst  = stage_addr + slot * CHUNK_BYTES;
            const char* src = gbase + (size_t)c * CHUNK_BYTES;
            asm volatile(
                "mbarrier.arrive.expect_tx.shared::cta.b64 _, [%0], %1;"
                :: "r"(mb), "n"(CHUNK_BYTES) : "memory");
            asm volatile(
                "cp.async.bulk.shared::cluster.global.mbarrier::complete_tx::bytes"
                " [%0], [%1], %2, [%3];"
                :: "r"(dst), "l"(src), "n"(CHUNK_BYTES), "r"(mb) : "memory");
        }
    };

    auto wait_chunk = [&](int c) {
        uint32_t mb     = mbar_addr + ((uint32_t)c & (RINGC - 1)) * 8;
        uint32_t parity = ((uint32_t)c >> 3) & 1u;
        asm volatile(
            "{\n\t.reg .pred P;\n\t"
            "W_%=:\n\t"
            "mbarrier.try_wait.parity.acquire.cta.shared::cta.b64 P, [%0], %1, 0x989680;\n\t"
            "@!P bra W_%=;\n\t}"
            :: "r"(mb), "r"(parity) : "memory");
    };

    float a[PSTATES];
    int   ilogacc = 0;                         // power-of-2 exponent accumulator
    float rho     = (tid == 0) ? 0.0f : 1.0f;  // lane0 rho=0 == m1 mask
    float h1p, h2p;                            // pipelined halos for next step

    auto make_h = [&]() {
        h1p = __shfl_up_sync(0xffffffffu, a[4], 1) * rho;
        h2p = __shfl_up_sync(0xffffffffu, a[3], 1) * rho;
    };

    // pipelined step: consumes h1p/h2p, produces next h1p/h2p mid-step
    auto step_p = [&](const float* __restrict__ row) {
        float p0 = fmaf(row[cls[0]], vm[0], evm[0]);
        float p1 = fmaf(row[cls[1]], vm[1], evm[1]);
        float p2 = fmaf(row[cls[2]], vm[2], evm[2]);
        float p3 = fmaf(row[cls[3]], vm[3], evm[3]);
        float p4 = fmaf(row[cls[4]], vm[4], evm[4]);
        float n3 = fmaf(a[1], m2[3], a[3] + a[2]) * p3;   // local-only first
        float n4 = fmaf(a[2], m2[4], a[4] + a[3]) * p4;
        float nh1 = __shfl_up_sync(0xffffffffu, n4, 1);   // next step's halos
        float nh2 = __shfl_up_sync(0xffffffffu, n3, 1);
        float n0 = fmaf(h2p,  m2[0], a[0] + h1p)  * p0;   // overlap with shfl
        float n1 = fmaf(h1p,  m2[1], a[1] + a[0]) * p1;
        float n2 = fmaf(a[0], m2[2], a[2] + a[1]) * p2;
        a[0] = n0; a[1] = n1; a[2] = n2; a[3] = n3; a[4] = n4;
        h1p = nh1 * rho; h2p = nh2 * rho;
    };

    // final step of a group: no pre-shfl (renorm follows)
    auto step_f = [&](const float* __restrict__ row) {
        float p0 = fmaf(row[cls[0]], vm[0], evm[0]);
        float p1 = fmaf(row[cls[1]], vm[1], evm[1]);
        float p2 = fmaf(row[cls[2]], vm[2], evm[2]);
        float p3 = fmaf(row[cls[3]], vm[3], evm[3]);
        float p4 = fmaf(row[cls[4]], vm[4], evm[4]);
        float n3 = fmaf(a[1], m2[3], a[3] + a[2]) * p3;
        float n4 = fmaf(a[2], m2[4], a[4] + a[3]) * p4;
        float n0 = fmaf(h2p,  m2[0], a[0] + h1p)  * p0;
        float n1 = fmaf(h1p,  m2[1], a[1] + a[0]) * p1;
        float n2 = fmaf(a[0], m2[2], a[2] + a[1]) * p2;
        a[0] = n0; a[1] = n1; a[2] = n2; a[3] = n3; a[4] = n4;
    };

    // guarded step (boundary chunks): fresh shfl each step
    auto step1g = [&](int t, const float* __restrict__ row) {
        if (t < Tlen) {
            float h1 = __shfl_up_sync(0xffffffffu, a[4], 1) * rho;
            float h2 = __shfl_up_sync(0xffffffffu, a[3], 1) * rho;
            float p0 = fmaf(row[cls[0]], vm[0], evm[0]);
            float p1 = fmaf(row[cls[1]], vm[1], evm[1]);
            float p2 = fmaf(row[cls[2]], vm[2], evm[2]);
            float p3 = fmaf(row[cls[3]], vm[3], evm[3]);
            float p4 = fmaf(row[cls[4]], vm[4], evm[4]);
            float n0 = fmaf(h2,   m2[0], a[0] + h1)   * p0;
            float n1 = fmaf(h1,   m2[1], a[1] + a[0]) * p1;
            float n2 = fmaf(a[0], m2[2], a[2] + a[1]) * p2;
            float n3 = fmaf(a[1], m2[3], a[3] + a[2]) * p3;
            float n4 = fmaf(a[2], m2[4], a[4] + a[3]) * p4;
            a[0] = n0; a[1] = n1; a[2] = n2; a[3] = n3; a[4] = n4;
        }
    };

    auto apply_scale = [&](float v) {
        int ebits = __float_as_int(v) >> 23;               // biased exponent
        int eprev = __shfl_up_sync(0xffffffffu, ebits, 1); // lane0: own
        ilogacc += ebits - 127;
        float rinv = __int_as_float((254 - ebits) << 23);  // 2^(127-e)
        int d = eprev - ebits;
        d = (d > 60) ? 60 : ((d < -126) ? -126 : d);
        rho = fminf(rho * __int_as_float((d + 127) << 23), 1e30f);
        #pragma unroll
        for (int j = 0; j < PSTATES; j++) a[j] *= rinv;
    };

    auto renorm_scan = [&]() {       // frontier-safe: adopt nearest active below
        float lm = fmaxf(fmaxf(fmaxf(a[0], a[1]), fmaxf(a[2], a[3])), a[4]);
        float v  = lm;
        #pragma unroll
        for (int d = 1; d < 32; d <<= 1) {
            float up = __shfl_up_sync(0xffffffffu, v, d);
            v = (v > 0.0f) ? v : up;
        }
        apply_scale(fmaxf(v, MFLOOR));
    };

    auto renorm_fast = [&]() {
        float lm = fmaxf(fmaxf(fmaxf(a[0], a[1]), fmaxf(a[2], a[3])), a[4]);
        apply_scale(fmaxf(lm, MFLOOR));
    };

    // fast 8-step group: pipeline invariant (h1p/h2p valid on entry and exit)
    auto group8 = [&](const float* __restrict__ rows, bool scan) {
        #pragma unroll
        for (int i = 0; i < 7; i++) step_p(rows + i * C_DIM);
        step_f(rows + 7 * C_DIM);
        if (scan) renorm_scan(); else renorm_fast();
        make_h();
    };

    // guarded 8-step group (boundary chunk)
    auto group8g = [&](int t0, const float* __restrict__ rows, bool scan) {
        #pragma unroll
        for (int i = 0; i < 8; i++) step1g(t0 + i, rows + i * C_DIM);
        if (scan) renorm_scan(); else renorm_fast();
        make_h();
    };

    // ---- prologue: issue chunks 0..RINGC-2 (7 x 16KB = 112KB in flight) ----
    for (int c = 0; c < RINGC - 1; c++) issue_chunk(c);

    // ---- chunk 0: init at t=0, guarded steps 1..15 ----
    wait_chunk(0);
    __syncwarp();
    issue_chunk(RINGC - 1);
    {
        const float* __restrict__ row0 = &stage[0];
        #pragma unroll
        for (int j = 0; j < PSTATES; j++) {
            int s   = tid * PSTATES + j;
            float p = fmaf(row0[cls[j]], vm[j], evm[j]);
            a[j]    = (s < 2) ? p : 0.0f;
        }
        #pragma unroll
        for (int i = 1; i < 8; i++) step1g(i, &stage[i * C_DIM]);
        renorm_scan();
        make_h();
        group8g(8, &stage[8 * C_DIM], true);
    }

    // ---- chunks 1..63 ----
    for (int c = 1; c < NCHUNK; c++) {
        wait_chunk(c);
        __syncwarp();                        // all lanes done with slot c-1
        issue_chunk(c + RINGC - 1);
        const float* __restrict__ rows = &stage[(c & (RINGC - 1)) * CHUNK * C_DIM];
        const int t0 = c * CHUNK;
        const bool scan = (c < SCANCH);
        if (t0 + CHUNK <= Tlen) {            // fast path: pipelined groups
            group8(rows, scan);
            group8(rows + 8 * C_DIM, scan);
        } else {                             // boundary chunk
            group8g(t0,     rows,             scan);
            group8g(t0 + 8, rows + 8 * C_DIM, scan);
        }
    }

    // ---- finalize: ll = logaddexp over the two end states ----
    __syncwarp();
    #pragma unroll
    for (int j = 0; j < PSTATES; j++) fin_a[tid * PSTATES + j] = a[j];
    fin_lc[tid] = (float)ilogacc * 0.6931471805599453f;
    __syncwarp();
    if (tid == 0) {
        int  sa = 2 * L;
        int  sb = 2 * L - 1;                  // L >= 1 per setup
        float xa = __logf(fmaxf(fin_a[sa], MFLOOR)) + fin_lc[sa / PSTATES];
        float xb = __logf(fmaxf(fin_a[sb], MFLOOR)) + fin_lc[sb / PSTATES];
        float mxx = fmaxf(xa, xb);
        float mnn = fminf(xa, xb);
        float ll  = mxx + __logf(1.0f + __expf(mnn - mxx));
        out[b] = -ll;
    }
}

extern "C" void kernel_launch(void* const* d_in, const int* in_sizes, int n_in,
                              void* d_out, int out_size) {
    const int*   y_true  = (const int*)  d_in[0];   // [B,64] int32
    const float* y_pred  = (const float*)d_in[1];   // [B,1024,256] fp32
    const int*   in_len  = (const int*)  d_in[2];   // [B,1] int32
    const int*   lab_len = (const int*)  d_in[3];   // [B,1] int32
    float*       out     = (float*)      d_out;     // [B,1] fp32

    cudaFuncSetAttribute(ctc_loss_kernel,
                         cudaFuncAttributeMaxDynamicSharedMemorySize,
                         RING_BYTES);

    const int B = out_size;                          // 128
    ctc_loss_kernel<<<B, 32, RING_BYTES>>>(y_true, y_pred, in_len, lab_len, out);
}

// round 13
// speedup vs baseline: 1.0014x; 1.0014x over previous
#include <cuda_runtime.h>
#include <cstdint>

// CTC batch cost, forward (loss only). B=128, T=1024, C=256 (blank=255),
// Lmax=64, S=129.
//
//  - one warp (one CTA) per batch element; 5 states/thread (160 >= 129, masked)
//  - probability-domain recurrence, per-thread power-of-2 block-floating-point
//    scales (integer exponent bookkeeping), frontier-safe scan renorm t<128
//  - bulk-copy streaming ring: one 16KB cp.async.bulk per chunk, mbarrier
//    complete_tx per slot (R11 base: 45.4us @1.44e-6)
//  - THIS ROUND: ONE-STEP EMISSION PRELOAD + pipelined halo shfl TOGETHER.
//    Each step issues the 5 LDS gathers for the NEXT step first, computes the
//    current step from registers (n3/n4 -> shfl immediately -> n0..n2), and
//    converts the landed raw loads at the end. Both latency chains (LDS ~33cy,
//    shfl ~26cy) are covered by a full step of independent work. One blocking
//    load per chunk re-establishes the invariant after the mbarrier wait.

#define T_DIM   1024
#define C_DIM   256
#define LMAX    64
#define PSTATES 5
#define CHUNK   16                        // rows per ring slot / wait
#define RINGC   8                         // ring slots
#define NCHUNK  (T_DIM / CHUNK)           // 64
#define SCANCH  8                         // chunks (t<128) using scan renorm
#define EPSF    1e-7f
#define MFLOOR  1e-37f
#define CHUNK_BYTES (CHUNK * C_DIM * 4)   // 16384
#define RING_BYTES  (RINGC * CHUNK_BYTES) // 131072

__global__ __launch_bounds__(32, 1)
void ctc_loss_kernel(const int*   __restrict__ y_true,   // [B, LMAX]
                     const float* __restrict__ y_pred,   // [B, T, C]
                     const int*   __restrict__ in_len,   // [B, 1]
                     const int*   __restrict__ lab_len,  // [B, 1]
                     float*       __restrict__ out)      // [B, 1]
{
    extern __shared__ __align__(128) float stage[];      // RINGC * 16KB ring
    __shared__ __align__(8) uint64_t mbar[RINGC];
    __shared__ float fin_a [32 * PSTATES];
    __shared__ float fin_lc[32];

    const int b   = blockIdx.x;
    const int tid = threadIdx.x;
    const char* __restrict__ gbase =
        (const char*)(y_pred + (size_t)b * T_DIM * C_DIM);
    const int L    = lab_len[b];
    const int Tlen = in_len[b];
    const int Smax = 2 * L + 1;
    const int* __restrict__ yb = y_true + b * LMAX;

    uint32_t stage_addr, mbar_addr;
    asm("{ .reg .u64 t; cvta.to.shared.u64 t, %1; cvt.u32.u64 %0, t; }"
        : "=r"(stage_addr) : "l"((const void*)stage));
    asm("{ .reg .u64 t; cvta.to.shared.u64 t, %1; cvt.u32.u64 %0, t; }"
        : "=r"(mbar_addr) : "l"((const void*)mbar));

    // ---- per-state constants ----
    int   cls[PSTATES];
    float vm [PSTATES];
    float evm[PSTATES];
    float m2 [PSTATES];
    #pragma unroll
    for (int j = 0; j < PSTATES; j++) {
        int s   = tid * PSTATES + j;
        int odd = s & 1;
        int li  = (s - 1) >> 1;
        int c   = (odd && li >= 0 && li < LMAX) ? yb[li] : (C_DIM - 1);
        bool valid = (s < Smax);
        cls[j] = c;
        vm [j] = valid ? 1.0f : 0.0f;
        evm[j] = valid ? EPSF : 0.0f;
        bool skip = odd && (s >= 3) && (li < LMAX) && (yb[li] != yb[li - 1]);
        m2 [j] = skip ? 1.0f : 0.0f;
    }

    // ---- mbarrier init ----
    if (tid == 0) {
        #pragma unroll
        for (int s = 0; s < RINGC; s++)
            asm volatile("mbarrier.init.shared.b64 [%0], 1;"
                         :: "r"(mbar_addr + s * 8) : "memory");
        asm volatile("fence.proxy.async.shared::cta;" ::: "memory");
    }
    __syncwarp();

    auto issue_chunk = [&](int c) {
        if (tid == 0 && c < NCHUNK) {
            uint32_t slot = (uint32_t)c & (RINGC - 1);
            uint32_t mb   = mbar_addr + slot * 8;
            uint32_t dst  = stage_addr + slot * CHUNK_BYTES;
            const char* src = gbase + (size_t)c * CHUNK_BYTES;
            asm volatile(
                "mbarrier.arrive.expect_tx.shared::cta.b64 _, [%0], %1;"
                :: "r"(mb), "n"(CHUNK_BYTES) : "memory");
            asm volatile(
                "cp.async.bulk.shared::cluster.global.mbarrier::complete_tx::bytes"
                " [%0], [%1], %2, [%3];"
                :: "r"(dst), "l"(src), "n"(CHUNK_BYTES), "r"(mb) : "memory");
        }
    };

    auto wait_chunk = [&](int c) {
        uint32_t mb     = mbar_addr + ((uint32_t)c & (RINGC - 1)) * 8;
        uint32_t parity = ((uint32_t)c >> 3) & 1u;
        asm volatile(
            "{\n\t.reg .pred P;\n\t"
            "W_%=:\n\t"
            "mbarrier.try_wait.parity.acquire.cta.shared::cta.b64 P, [%0], %1, 0x989680;\n\t"
            "@!P bra W_%=;\n\t}"
            :: "r"(mb), "r"(parity) : "memory");
    };

    float a[PSTATES];
    float pc[PSTATES];                         // current step's emission probs
    int   ilogacc = 0;                         // power-of-2 exponent accumulator
    float rho     = (tid == 0) ? 0.0f : 1.0f;  // lane0 rho=0 == m1 mask
    float h1p, h2p;                            // pipelined halos for next step

    auto make_h = [&]() {
        h1p = __shfl_up_sync(0xffffffffu, a[4], 1) * rho;
        h2p = __shfl_up_sync(0xffffffffu, a[3], 1) * rho;
    };

    auto load_pc = [&](const float* __restrict__ row) {   // blocking convert
        pc[0] = fmaf(row[cls[0]], vm[0], evm[0]);
        pc[1] = fmaf(row[cls[1]], vm[1], evm[1]);
        pc[2] = fmaf(row[cls[2]], vm[2], evm[2]);
        pc[3] = fmaf(row[cls[3]], vm[3], evm[3]);
        pc[4] = fmaf(row[cls[4]], vm[4], evm[4]);
    };

    // full pipelined step: uses pc + h1p/h2p, preloads next row, renews both
    auto step_pp = [&](const float* __restrict__ nxt) {
        float r0 = nxt[cls[0]], r1 = nxt[cls[1]], r2 = nxt[cls[2]],
              r3 = nxt[cls[3]], r4 = nxt[cls[4]];          // LDS issued early
        float n3 = fmaf(a[1], m2[3], a[3] + a[2]) * pc[3]; // local-only first
        float n4 = fmaf(a[2], m2[4], a[4] + a[3]) * pc[4];
        float nh1 = __shfl_up_sync(0xffffffffu, n4, 1);    // next halos fly now
        float nh2 = __shfl_up_sync(0xffffffffu, n3, 1);
        float n0 = fmaf(h2p,  m2[0], a[0] + h1p)  * pc[0];
        float n1 = fmaf(h1p,  m2[1], a[1] + a[0]) * pc[1];
        float n2 = fmaf(a[0], m2[2], a[2] + a[1]) * pc[2];
        a[0] = n0; a[1] = n1; a[2] = n2; a[3] = n3; a[4] = n4;
        h1p = nh1 * rho; h2p = nh2 * rho;
        pc[0] = fmaf(r0, vm[0], evm[0]);                   // landed by now
        pc[1] = fmaf(r1, vm[1], evm[1]);
        pc[2] = fmaf(r2, vm[2], evm[2]);
        pc[3] = fmaf(r3, vm[3], evm[3]);
        pc[4] = fmaf(r4, vm[4], evm[4]);
    };

    // final step of a group: no halo shfl (renorm + make_h follow)
    auto step_fin = [&]() {
        float n3 = fmaf(a[1], m2[3], a[3] + a[2]) * pc[3];
        float n4 = fmaf(a[2], m2[4], a[4] + a[3]) * pc[4];
        float n0 = fmaf(h2p,  m2[0], a[0] + h1p)  * pc[0];
        float n1 = fmaf(h1p,  m2[1], a[1] + a[0]) * pc[1];
        float n2 = fmaf(a[0], m2[2], a[2] + a[1]) * pc[2];
        a[0] = n0; a[1] = n1; a[2] = n2; a[3] = n3; a[4] = n4;
    };

    // final step + preload of the NEXT group's first row (same ring slot)
    auto step_fin_pre = [&](const float* __restrict__ nxt) {
        float r0 = nxt[cls[0]], r1 = nxt[cls[1]], r2 = nxt[cls[2]],
              r3 = nxt[cls[3]], r4 = nxt[cls[4]];
        step_fin();
        pc[0] = fmaf(r0, vm[0], evm[0]);
        pc[1] = fmaf(r1, vm[1], evm[1]);
        pc[2] = fmaf(r2, vm[2], evm[2]);
        pc[3] = fmaf(r3, vm[3], evm[3]);
        pc[4] = fmaf(r4, vm[4], evm[4]);
    };

    // guarded step (boundary chunks only): fresh shfl + direct gather
    auto step1g = [&](int t, const float* __restrict__ row) {
        if (t < Tlen) {
            float h1 = __shfl_up_sync(0xffffffffu, a[4], 1) * rho;
            float h2 = __shfl_up_sync(0xffffffffu, a[3], 1) * rho;
            float p0 = fmaf(row[cls[0]], vm[0], evm[0]);
            float p1 = fmaf(row[cls[1]], vm[1], evm[1]);
            float p2 = fmaf(row[cls[2]], vm[2], evm[2]);
            float p3 = fmaf(row[cls[3]], vm[3], evm[3]);
            float p4 = fmaf(row[cls[4]], vm[4], evm[4]);
            float n0 = fmaf(h2,   m2[0], a[0] + h1)   * p0;
            float n1 = fmaf(h1,   m2[1], a[1] + a[0]) * p1;
            float n2 = fmaf(a[0], m2[2], a[2] + a[1]) * p2;
            float n3 = fmaf(a[1], m2[3], a[3] + a[2]) * p3;
            float n4 = fmaf(a[2], m2[4], a[4] + a[3]) * p4;
            a[0] = n0; a[1] = n1; a[2] = n2; a[3] = n3; a[4] = n4;
        }
    };

    auto apply_scale = [&](float v) {
        int ebits = __float_as_int(v) >> 23;               // biased exponent
        int eprev = __shfl_up_sync(0xffffffffu, ebits, 1); // lane0: own
        ilogacc += ebits - 127;
        float rinv = __int_as_float((254 - ebits) << 23);  // 2^(127-e)
        int d = eprev - ebits;
        d = (d > 60) ? 60 : ((d < -126) ? -126 : d);
        rho = fminf(rho * __int_as_float((d + 127) << 23), 1e30f);
        #pragma unroll
        for (int j = 0; j < PSTATES; j++) a[j] *= rinv;
    };

    auto renorm_scan = [&]() {       // frontier-safe: adopt nearest active below
        float lm = fmaxf(fmaxf(fmaxf(a[0], a[1]), fmaxf(a[2], a[3])), a[4]);
        float v  = lm;
        #pragma unroll
        for (int d = 1; d < 32; d <<= 1) {
            float up = __shfl_up_sync(0xffffffffu, v, d);
            v = (v > 0.0f) ? v : up;
        }
        apply_scale(fmaxf(v, MFLOOR));
    };

    auto renorm_fast = [&]() {
        float lm = fmaxf(fmaxf(fmaxf(a[0], a[1]), fmaxf(a[2], a[3])), a[4]);
        apply_scale(fmaxf(lm, MFLOOR));
    };

    // first group of a chunk: preloads through rows[8] for the second group
    auto group8_cont = [&](const float* __restrict__ rows, bool scan) {
        #pragma unroll
        for (int i = 0; i < 7; i++) step_pp(rows + (i + 1) * C_DIM);
        step_fin_pre(rows + 8 * C_DIM);
        if (scan) renorm_scan(); else renorm_fast();
        make_h();
    };

    // second group of a chunk: no cross-chunk preload
    auto group8_last = [&](const float* __restrict__ rows, bool scan) {
        #pragma unroll
        for (int i = 0; i < 7; i++) step_pp(rows + (i + 1) * C_DIM);
        step_fin();
        if (scan) renorm_scan(); else renorm_fast();
        make_h();
    };

    // guarded 8-step group (boundary chunk)
    auto group8g = [&](int t0, const float* __restrict__ rows, bool scan) {
        #pragma unroll
        for (int i = 0; i < 8; i++) step1g(t0 + i, rows + i * C_DIM);
        if (scan) renorm_scan(); else renorm_fast();
        make_h();
    };

    // ---- prologue: issue chunks 0..RINGC-2 (7 x 16KB = 112KB in flight) ----
    for (int c = 0; c < RINGC - 1; c++) issue_chunk(c);

    // ---- chunk 0: init at t=0, guarded steps 1..15 ----
    wait_chunk(0);
    __syncwarp();
    issue_chunk(RINGC - 1);
    {
        const float* __restrict__ row0 = &stage[0];
        #pragma unroll
        for (int j = 0; j < PSTATES; j++) {
            int s   = tid * PSTATES + j;
            float p = fmaf(row0[cls[j]], vm[j], evm[j]);
            a[j]    = (s < 2) ? p : 0.0f;
        }
        #pragma unroll
        for (int i = 1; i < 8; i++) step1g(i, &stage[i * C_DIM]);
        renorm_scan();
        make_h();
        group8g(8, &stage[8 * C_DIM], true);
    }

    // ---- chunks 1..63 ----
    for (int c = 1; c < NCHUNK; c++) {
        wait_chunk(c);
        __syncwarp();                        // all lanes done with slot c-1
        issue_chunk(c + RINGC - 1);
        const float* __restrict__ rows = &stage[(c & (RINGC - 1)) * CHUNK * C_DIM];
        const int t0 = c * CHUNK;
        const bool scan = (c < SCANCH);
        if (t0 + CHUNK <= Tlen) {            // fast path: fully pipelined
            load_pc(rows);                   // one exposed LDS per chunk
            group8_cont(rows, scan);         // exits with pc = P(rows[8])
            group8_last(rows + 8 * C_DIM, scan);
        } else {                             // boundary chunk
            group8g(t0,     rows,             scan);
            group8g(t0 + 8, rows + 8 * C_DIM, scan);
        }
    }

    // ---- finalize: ll = logaddexp over the two end states ----
    __syncwarp();
    #pragma unroll
    for (int j = 0; j < PSTATES; j++) fin_a[tid * PSTATES + j] = a[j];
    fin_lc[tid] = (float)ilogacc * 0.6931471805599453f;
    __syncwarp();
    if (tid == 0) {
        int  sa = 2 * L;
        int  sb = 2 * L - 1;                  // L >= 1 per setup
        float xa = __logf(fmaxf(fin_a[sa], MFLOOR)) + fin_lc[sa / PSTATES];
        float xb = __logf(fmaxf(fin_a[sb], MFLOOR)) + fin_lc[sb / PSTATES];
        float mxx = fmaxf(xa, xb);
        float mnn = fminf(xa, xb);
        float ll  = mxx + __logf(1.0f + __expf(mnn - mxx));
        out[b] = -ll;
    }
}

extern "C" void kernel_launch(void* const* d_in, const int* in_sizes, int n_in,
                              void* d_out, int out_size) {
    const int*   y_true  = (const int*)  d_in[0];   // [B,64] int32
    const float* y_pred  = (const float*)d_in[1];   // [B,1024,256] fp32
    const int*   in_len  = (const int*)  d_in[2];   // [B,1] int32
    const int*   lab_len = (const int*)  d_in[3];   // [B,1] int32
    float*       out     = (float*)      d_out;     // [B,1] fp32

    cudaFuncSetAttribute(ctc_loss_kernel,
                         cudaFuncAttributeMaxDynamicSharedMemorySize,
                         RING_BYTES);

    const int B = out_size;                          // 128
    ctc_loss_kernel<<<B, 32, RING_BYTES>>>(y_true, y_pred, in_len, lab_len, out);
}

// round 14
// speedup vs baseline: 1.4242x; 1.4222x over previous
#include <cuda_runtime.h>
#include <cstdint>

// CTC batch cost, forward (loss only). B=128, T=1024, C=256 (blank=255),
// Lmax=64, S=129.
//
// BIDIRECTIONAL SPLIT (this round): one CTA per batch element, 2 warps.
//   warp 0: forward alpha,  t = 0..511   (R11-style steps, shfl_up halos)
//   warp 1: backward gamma, t = 1023..512 (mirrored: shfl_down halos,
//           source-based skip mask, lane31 rho_b=0, scan adopts from above)
//   combine: ll = sum_s alpha_511(s) * (g512(s) + g512(s+1) + skip*g512(s+2))
//   done in log space by warp 0 (exact per-thread scale bookkeeping).
// Serial chain halves: 1024 -> 512 steps/warp. Each warp has its own
// 4-slot x 16KB bulk-copy ring + mbarriers (proven R10/R11 transport).

#define T_DIM   1024
#define C_DIM   256
#define LMAX    64
#define PSTATES 5
#define HALF    512
#define CHUNK   16
#define RINGC   4                         // slots per warp
#define HCHUNK  (HALF / CHUNK)            // 32 chunks per half
#define SCANCH  8                         // chunks using frontier-safe scan
#define EPSF    1e-7f
#define MFLOOR  1e-37f
#define NEGL    -1e30f
#define CHUNK_BYTES (CHUNK * C_DIM * 4)   // 16384
#define RING_BYTES  (2 * RINGC * CHUNK_BYTES) // 131072

__global__ __launch_bounds__(64, 1)
void ctc_loss_kernel(const int*   __restrict__ y_true,   // [B, LMAX]
                     const float* __restrict__ y_pred,   // [B, T, C]
                     const int*   __restrict__ in_len,   // [B, 1]
                     const int*   __restrict__ lab_len,  // [B, 1]
                     float*       __restrict__ out)      // [B, 1]
{
    extern __shared__ __align__(128) float stage[];      // 2 rings, 64KB each
    __shared__ __align__(8) uint64_t mbar[2 * RINGC];
    __shared__ float fa [32 * PSTATES];   // alpha_511 by state
    __shared__ float fg [32 * PSTATES];   // gamma_512 by state
    __shared__ float flc[32], glc[32];    // per-lane log scales

    const int b    = blockIdx.x;
    const int tid  = threadIdx.x;
    const int wid  = tid >> 5;
    const int lane = tid & 31;
    const char* __restrict__ gbase =
        (const char*)(y_pred + (size_t)b * T_DIM * C_DIM);
    const int L    = lab_len[b];
    const int Tlen = in_len[b];
    const int Smax = 2 * L + 1;
    const int* __restrict__ yb = y_true + b * LMAX;

    uint32_t stage_addr, mbar_addr;
    asm("{ .reg .u64 t; cvta.to.shared.u64 t, %1; cvt.u32.u64 %0, t; }"
        : "=r"(stage_addr) : "l"((const void*)stage));
    asm("{ .reg .u64 t; cvta.to.shared.u64 t, %1; cvt.u32.u64 %0, t; }"
        : "=r"(mbar_addr) : "l"((const void*)mbar));

    // ---- per-state constants (lane-based; both warps use same layout) ----
    int   cls[PSTATES];
    float vm [PSTATES];
    float evm[PSTATES];
    #pragma unroll
    for (int j = 0; j < PSTATES; j++) {
        int s   = lane * PSTATES + j;
        int odd = s & 1;
        int li  = (s - 1) >> 1;
        int c   = (odd && li >= 0 && li < LMAX) ? yb[li] : (C_DIM - 1);
        bool valid = (s < Smax);
        cls[j] = c;
        vm [j] = valid ? 1.0f : 0.0f;
        evm[j] = valid ? EPSF : 0.0f;
    }

    if (tid == 0) {
        #pragma unroll
        for (int s = 0; s < 2 * RINGC; s++)
            asm volatile("mbarrier.init.shared.b64 [%0], 1;"
                         :: "r"(mbar_addr + s * 8) : "memory");
        asm volatile("fence.proxy.async.shared::cta;" ::: "memory");
    }
    __syncthreads();

    // generic per-warp ring helpers -------------------------------------
    const int warpbase = wid * RINGC;
    auto issue_k = [&](int k) {              // k-th processed chunk this warp
        if (lane == 0 && k < HCHUNK) {
            int gchunk = (wid == 0) ? k : (63 - k);
            uint32_t slot = (uint32_t)(warpbase + (k & (RINGC - 1)));
            uint32_t mb   = mbar_addr + slot * 8;
            uint32_t dst  = stage_addr + slot * CHUNK_BYTES;
            const char* src = gbase + (size_t)gchunk * CHUNK_BYTES;
            asm volatile(
                "mbarrier.arrive.expect_tx.shared::cta.b64 _, [%0], %1;"
                :: "r"(mb), "n"(CHUNK_BYTES) : "memory");
            asm volatile(
                "cp.async.bulk.shared::cluster.global.mbarrier::complete_tx::bytes"
                " [%0], [%1], %2, [%3];"
                :: "r"(dst), "l"(src), "n"(CHUNK_BYTES), "r"(mb) : "memory");
        }
    };
    auto wait_k = [&](int k) {
        uint32_t mb = mbar_addr + (uint32_t)(warpbase + (k & (RINGC - 1))) * 8;
        uint32_t parity = ((uint32_t)k >> 2) & 1u;
        asm volatile(
            "{\n\t.reg .pred P;\n\t"
            "W_%=:\n\t"
            "mbarrier.try_wait.parity.acquire.cta.shared::cta.b64 P, [%0], %1, 0x989680;\n\t"
            "@!P bra W_%=;\n\t}"
            :: "r"(mb), "r"(parity) : "memory");
    };
    auto slot_rows = [&](int k) -> const float* {
        return stage + (size_t)(warpbase + (k & (RINGC - 1))) * (CHUNK_BYTES / 4);
    };

    if (wid == 0) {
        // ================= FORWARD WARP: alpha, t = 0..511 =================
        float m2[PSTATES];
        #pragma unroll
        for (int j = 0; j < PSTATES; j++) {
            int s  = lane * PSTATES + j;
            int li = (s - 1) >> 1;
            bool skip = (s & 1) && (s >= 3) && (li < LMAX) && (yb[li] != yb[li - 1]);
            m2[j] = skip ? 1.0f : 0.0f;
        }
        float a[PSTATES];
        int   ilog = 0;
        float rho  = (lane == 0) ? 0.0f : 1.0f;

        auto step1u = [&](const float* __restrict__ row) {
            float h1 = __shfl_up_sync(0xffffffffu, a[4], 1) * rho;
            float h2 = __shfl_up_sync(0xffffffffu, a[3], 1) * rho;
            float p0 = fmaf(row[cls[0]], vm[0], evm[0]);
            float p1 = fmaf(row[cls[1]], vm[1], evm[1]);
            float p2 = fmaf(row[cls[2]], vm[2], evm[2]);
            float p3 = fmaf(row[cls[3]], vm[3], evm[3]);
            float p4 = fmaf(row[cls[4]], vm[4], evm[4]);
            float n0 = fmaf(h2,   m2[0], a[0] + h1)   * p0;
            float n1 = fmaf(h1,   m2[1], a[1] + a[0]) * p1;
            float n2 = fmaf(a[0], m2[2], a[2] + a[1]) * p2;
            float n3 = fmaf(a[1], m2[3], a[3] + a[2]) * p3;
            float n4 = fmaf(a[2], m2[4], a[4] + a[3]) * p4;
            a[0] = n0; a[1] = n1; a[2] = n2; a[3] = n3; a[4] = n4;
        };
        auto step1g = [&](int t, const float* __restrict__ row) {
            if (t < Tlen) step1u(row);
        };
        auto apply_scale = [&](float v) {
            int ebits = __float_as_int(v) >> 23;
            int eprev = __shfl_up_sync(0xffffffffu, ebits, 1);
            ilog += ebits - 127;
            float rinv = __int_as_float((254 - ebits) << 23);
            int d = eprev - ebits;
            d = (d > 60) ? 60 : ((d < -126) ? -126 : d);
            rho = fminf(rho * __int_as_float((d + 127) << 23), 1e30f);
            #pragma unroll
            for (int j = 0; j < PSTATES; j++) a[j] *= rinv;
        };
        auto renorm_scan = [&]() {
            float v = fmaxf(fmaxf(fmaxf(a[0], a[1]), fmaxf(a[2], a[3])), a[4]);
            #pragma unroll
            for (int d = 1; d < 32; d <<= 1) {
                float up = __shfl_up_sync(0xffffffffu, v, d);
                v = (v > 0.0f) ? v : up;
            }
            apply_scale(fmaxf(v, MFLOOR));
        };
        auto renorm_fast = [&]() {
            float v = fmaxf(fmaxf(fmaxf(a[0], a[1]), fmaxf(a[2], a[3])), a[4]);
            apply_scale(fmaxf(v, MFLOOR));
        };

        for (int k = 0; k < RINGC - 1; k++) issue_k(k);

        // chunk 0: init t=0 + guarded steps
        wait_k(0);
        __syncwarp();
        issue_k(RINGC - 1);
        {
            const float* __restrict__ rows = slot_rows(0);
            #pragma unroll
            for (int j = 0; j < PSTATES; j++) {
                int s   = lane * PSTATES + j;
                float p = fmaf(rows[cls[j]], vm[j], evm[j]);
                a[j]    = (s < 2) ? p : 0.0f;
            }
            #pragma unroll
            for (int i = 1; i < 8; i++) step1g(i, rows + i * C_DIM);
            renorm_scan();
            #pragma unroll
            for (int i = 8; i < CHUNK; i++) step1g(i, rows + i * C_DIM);
            renorm_scan();
        }
        for (int k = 1; k < HCHUNK; k++) {
            wait_k(k);
            __syncwarp();
            issue_k(k + RINGC - 1);
            const float* __restrict__ rows = slot_rows(k);
            const int t0 = k * CHUNK;
            const bool scan = (k < SCANCH);
            if (t0 + CHUNK <= Tlen) {
                #pragma unroll
                for (int i = 0; i < 8; i++) step1u(rows + i * C_DIM);
                if (scan) renorm_scan(); else renorm_fast();
                #pragma unroll
                for (int i = 8; i < CHUNK; i++) step1u(rows + i * C_DIM);
                if (scan) renorm_scan(); else renorm_fast();
            } else {
                #pragma unroll
                for (int i = 0; i < 8; i++) step1g(t0 + i, rows + i * C_DIM);
                if (scan) renorm_scan(); else renorm_fast();
                #pragma unroll
                for (int i = 8; i < CHUNK; i++) step1g(t0 + i, rows + i * C_DIM);
                if (scan) renorm_scan(); else renorm_fast();
            }
        }
        #pragma unroll
        for (int j = 0; j < PSTATES; j++) fa[lane * PSTATES + j] = a[j];
        flc[lane] = (float)ilog * 0.6931471805599453f;
    } else {
        // ================ BACKWARD WARP: gamma, t = 1023..512 ==============
        float m2b[PSTATES];                 // skip s -> s+2 (source-based)
        #pragma unroll
        for (int j = 0; j < PSTATES; j++) {
            int s  = lane * PSTATES + j;
            int li = (s - 1) >> 1;
            bool skip = (s & 1) && (li + 1 < LMAX) && (yb[li + 1] != yb[li]);
            m2b[j] = skip ? 1.0f : 0.0f;
        }
        float g[PSTATES];
        int   ilog  = 0;
        float rho_b = (lane == 31) ? 0.0f : 1.0f;
        bool  virgin = true;
        #pragma unroll
        for (int j = 0; j < PSTATES; j++) {
            int s = lane * PSTATES + j;
            g[j] = (s == 2 * L || s == 2 * L - 1) ? 1.0f : 0.0f;
        }

        auto stepbu = [&](const float* __restrict__ row) {
            float h5 = __shfl_down_sync(0xffffffffu, g[0], 1) * rho_b;
            float h6 = __shfl_down_sync(0xffffffffu, g[1], 1) * rho_b;
            float p0 = fmaf(row[cls[0]], vm[0], evm[0]);
            float p1 = fmaf(row[cls[1]], vm[1], evm[1]);
            float p2 = fmaf(row[cls[2]], vm[2], evm[2]);
            float p3 = fmaf(row[cls[3]], vm[3], evm[3]);
            float p4 = fmaf(row[cls[4]], vm[4], evm[4]);
            float n0 = fmaf(m2b[0], g[2], g[0] + g[1]) * p0;
            float n1 = fmaf(m2b[1], g[3], g[1] + g[2]) * p1;
            float n2 = fmaf(m2b[2], g[4], g[2] + g[3]) * p2;
            float n3 = fmaf(m2b[3], h5,   g[3] + g[4]) * p3;
            float n4 = fmaf(m2b[4], h6,   g[4] + h5  ) * p4;
            g[0] = n0; g[1] = n1; g[2] = n2; g[3] = n3; g[4] = n4;
        };
        auto stepbg = [&](int t, const float* __restrict__ row) {
            if (t < Tlen) {
                if (virgin) {                 // last real step: emission only
                    #pragma unroll
                    for (int j = 0; j < PSTATES; j++)
                        g[j] *= fmaf(row[cls[j]], vm[j], evm[j]);
                    virgin = false;
                } else stepbu(row);
            }
        };
        auto apply_scale_b = [&](float v) {
            int ebits = __float_as_int(v) >> 23;
            int enext = __shfl_down_sync(0xffffffffu, ebits, 1);
            ilog += ebits - 127;
            float rinv = __int_as_float((254 - ebits) << 23);
            int d = enext - ebits;
            d = (d > 60) ? 60 : ((d < -126) ? -126 : d);
            rho_b = fminf(rho_b * __int_as_float((d + 127) << 23), 1e30f);
            #pragma unroll
            for (int j = 0; j < PSTATES; j++) g[j] *= rinv;
        };
        auto renorm_scan_b = [&]() {          // adopt nearest active ABOVE
            float v = fmaxf(fmaxf(fmaxf(g[0], g[1]), fmaxf(g[2], g[3])), g[4]);
            #pragma unroll
            for (int d = 1; d < 32; d <<= 1) {
                float dn = __shfl_down_sync(0xffffffffu, v, d);
                v = (v > 0.0f) ? v : dn;
            }
            apply_scale_b(fmaxf(v, MFLOOR));
        };
        auto renorm_fast_b = [&]() {
            float v = fmaxf(fmaxf(fmaxf(g[0], g[1]), fmaxf(g[2], g[3])), g[4]);
            apply_scale_b(fmaxf(v, MFLOOR));
        };

        for (int k = 0; k < RINGC - 1; k++) issue_k(k);

        for (int k = 0; k < HCHUNK; k++) {
            wait_k(k);
            __syncwarp();
            issue_k(k + RINGC - 1);
            const float* __restrict__ rows = slot_rows(k);
            const int c  = 63 - k;
            const int tb = c * CHUNK;
            const bool scan = (k < SCANCH);
            if (!virgin && (tb + CHUNK <= Tlen)) {   // fast: branch-free
                #pragma unroll
                for (int i = CHUNK - 1; i >= 8; i--) stepbu(rows + i * C_DIM);
                if (scan) renorm_scan_b(); else renorm_fast_b();
                #pragma unroll
                for (int i = 7; i >= 0; i--) stepbu(rows + i * C_DIM);
                if (scan) renorm_scan_b(); else renorm_fast_b();
            } else {                                  // guarded (k==0 / tail)
                #pragma unroll
                for (int i = CHUNK - 1; i >= 8; i--) stepbg(tb + i, rows + i * C_DIM);
                if (scan) renorm_scan_b(); else renorm_fast_b();
                #pragma unroll
                for (int i = 7; i >= 0; i--) stepbg(tb + i, rows + i * C_DIM);
                if (scan) renorm_scan_b(); else renorm_fast_b();
            }
        }
        #pragma unroll
        for (int j = 0; j < PSTATES; j++) fg[lane * PSTATES + j] = g[j];
        glc[lane] = (float)ilog * 0.6931471805599453f;
    }

    __syncthreads();

    // ===================== COMBINE (warp 0, log space) =====================
    if (wid == 0) {
        if (Tlen > HALF) {
            float vals[PSTATES];
            float M = NEGL;
            #pragma unroll
            for (int j = 0; j < PSTATES; j++) {
                int s = lane * PSTATES + j;
                float v = NEGL;
                if (s < Smax) {
                    float la = __logf(fmaxf(fa[s], MFLOOR)) + flc[lane];
                    float t0 = __logf(fmaxf(fg[s], MFLOOR)) + glc[lane];
                    float t1 = NEGL, t2 = NEGL;
                    if (s + 1 < Smax)
                        t1 = __logf(fmaxf(fg[s + 1], MFLOOR)) + glc[(s + 1) / PSTATES];
                    if ((s & 1) && (s + 2 < Smax)) {
                        int li = (s - 1) >> 1;
                        if (li + 1 < LMAX && yb[li + 1] != yb[li])
                            t2 = __logf(fmaxf(fg[s + 2], MFLOOR)) + glc[(s + 2) / PSTATES];
                    }
                    float m3 = fmaxf(t0, fmaxf(t1, t2));
                    float lmix = m3 + __logf(__expf(t0 - m3) + __expf(t1 - m3) +
                                             __expf(t2 - m3));
                    v = la + lmix;
                }
                vals[j] = v;
                M = fmaxf(M, v);
            }
            #pragma unroll
            for (int o = 16; o > 0; o >>= 1)
                M = fmaxf(M, __shfl_xor_sync(0xffffffffu, M, o));
            float ssum = 0.0f;
            #pragma unroll
            for (int j = 0; j < PSTATES; j++) ssum += __expf(vals[j] - M);
            #pragma unroll
            for (int o = 16; o > 0; o >>= 1)
                ssum += __shfl_xor_sync(0xffffffffu, ssum, o);
            if (lane == 0) out[b] = -(M + __logf(ssum));
        } else if (lane == 0) {
            // all real steps in the forward half: alpha_511 is final (frozen)
            int  sa = 2 * L, sb = 2 * L - 1;
            float xa = __logf(fmaxf(fa[sa], MFLOOR)) + flc[sa / PSTATES];
            float xb = __logf(fmaxf(fa[sb], MFLOOR)) + flc[sb / PSTATES];
            float mxx = fmaxf(xa, xb), mnn = fminf(xa, xb);
            out[b] = -(mxx + __logf(1.0f + __expf(mnn - mxx)));
        }
    }
}

extern "C" void kernel_launch(void* const* d_in, const int* in_sizes, int n_in,
                              void* d_out, int out_size) {
    const int*   y_true  = (const int*)  d_in[0];   // [B,64] int32
    const float* y_pred  = (const float*)d_in[1];   // [B,1024,256] fp32
    const int*   in_len  = (const int*)  d_in[2];   // [B,1] int32
    const int*   lab_len = (const int*)  d_in[3];   // [B,1] int32
    float*       out     = (float*)      d_out;     // [B,1] fp32

    cudaFuncSetAttribute(ctc_loss_kernel,
                         cudaFuncAttributeMaxDynamicSharedMemorySize,
                         RING_BYTES);

    const int B = out_size;                          // 128
    ctc_loss_kernel<<<B, 64, RING_BYTES>>>(y_true, y_pred, in_len, lab_len, out);
}